// round 16
// baseline (speedup 1.0000x reference)
#include <cuda_runtime.h>
#include <cuda_fp16.h>

#define DIMC 256
#define RESV 256
#define H2 128
#define HEADS 8
#define HD 32
#define NPIX 64
#define NWIN 512
#define PIXTOT (NWIN * NPIX)   // 32768
#define ATTN_SCALE 0.17677669529663687f
#define SROW 68                // padded smem row stride (floats)
#define AROWH 72               // attn_av padded attn row stride (halfs, 144B rows)
#define PSROW 132              // proj smem row stride (floats), 128-wide tiles

typedef unsigned long long ull;

// ---- packed fp32x2 helpers (FFMA2 — only reachable via PTX fma.rn.f32x2) ----
__device__ __forceinline__ void ffma2(ull& d, ull a, ull b) {
    asm("fma.rn.f32x2 %0, %1, %2, %0;" : "+l"(d) : "l"(a), "l"(b));
}
__device__ __forceinline__ ull pack2(float lo, float hi) {
    ull r; asm("mov.b64 %0, {%1, %2};" : "=l"(r) : "f"(lo), "f"(hi)); return r;
}
__device__ __forceinline__ float2 unpack2(ull v) {
    float2 r; asm("mov.b64 {%0, %1}, %2;" : "=f"(r.x), "=f"(r.y) : "l"(v)); return r;
}
__device__ __forceinline__ ull h2_to_pack2(unsigned int h2) {
    float2 f = __half22float2(*(__half2*)&h2);
    return pack2(f.x, f.y);
}
__device__ __forceinline__ unsigned int f2_to_h2(float lo, float hi) {
    __half2 h = __floats2half2_rn(lo, hi);
    return *(unsigned int*)&h;
}

// ---------------- scratch (static device allocations; no cudaMalloc) -------
__device__ float  g_ll[2 * DIMC * H2 * H2];    // ll stays fp32 (seeds the head chain)
__device__ __half g_lh16[2 * DIMC * H2 * H2];  // fp16 bands
__device__ __half g_hl16[2 * DIMC * H2 * H2];
__device__ __half g_hh16[2 * DIMC * H2 * H2];
__device__ __half g_attnh[NWIN * HEADS * NPIX * NPIX]; // softmax'd attn fp16, [wh][n][m]
__device__ __half g_atth[DIMC * PIXTOT];  // relu(attention out) fp16, [c][pix]
__device__ float g_bias[HEADS * NPIX * NPIX];

// ---------------- K0: expand attention bias table ---------------------------
__global__ void bias_kernel(const float* __restrict__ ab, const int* __restrict__ bidx) {
    int i = blockIdx.x * 256 + threadIdx.x;     // 32768 total
    int h = i >> 12;
    g_bias[i] = ab[h * 64 + bidx[i & 4095]];
}

// ---------------- K1: wavelet transform (depthwise 2x2 stride 2) -----------
// 2 output pixels per thread. ll stored fp32, lh/hl/hh stored fp16.
__global__ void wt_kernel(const float* __restrict__ x, const float* __restrict__ wt) {
    int t  = threadIdx.x;          // 0..127
    int tx = t & 63;               // x-pair index: outputs x = 2tx, 2tx+1
    int y  = 2 * blockIdx.x + (t >> 6);   // 0..127
    int bc = blockIdx.y;           // 0..511
    int c  = bc & 255;

    const float4 f0 = __ldg((const float4*)&wt[(4 * c + 0) * 4]);
    const float4 f1 = __ldg((const float4*)&wt[(4 * c + 1) * 4]);
    const float4 f2 = __ldg((const float4*)&wt[(4 * c + 2) * 4]);
    const float4 f3 = __ldg((const float4*)&wt[(4 * c + 3) * 4]);

    int ib = (bc * RESV + 2 * y) * RESV + 4 * tx;
    float4 p0 = *(const float4*)&x[ib];
    float4 p1 = *(const float4*)&x[ib + RESV];

    ull A0 = pack2(p0.x, p0.z), A1 = pack2(p0.y, p0.w);
    ull A2 = pack2(p1.x, p1.z), A3 = pack2(p1.y, p1.w);

    ull r0 = 0, r1 = 0, r2 = 0, r3 = 0;
    ffma2(r0, A0, pack2(f0.x, f0.x)); ffma2(r0, A1, pack2(f0.y, f0.y));
    ffma2(r0, A2, pack2(f0.z, f0.z)); ffma2(r0, A3, pack2(f0.w, f0.w));
    ffma2(r1, A0, pack2(f1.x, f1.x)); ffma2(r1, A1, pack2(f1.y, f1.y));
    ffma2(r1, A2, pack2(f1.z, f1.z)); ffma2(r1, A3, pack2(f1.w, f1.w));
    ffma2(r2, A0, pack2(f2.x, f2.x)); ffma2(r2, A1, pack2(f2.y, f2.y));
    ffma2(r2, A2, pack2(f2.z, f2.z)); ffma2(r2, A3, pack2(f2.w, f2.w));
    ffma2(r3, A0, pack2(f3.x, f3.x)); ffma2(r3, A1, pack2(f3.y, f3.y));
    ffma2(r3, A2, pack2(f3.z, f3.z)); ffma2(r3, A3, pack2(f3.w, f3.w));

    int ob = (bc * H2 + y) * H2 + 2 * tx;
    *(float2*)&g_ll[ob] = unpack2(r0);
    float2 u1 = unpack2(r1), u2 = unpack2(r2), u3 = unpack2(r3);
    *(unsigned int*)&g_lh16[ob] = f2_to_h2(u1.x, u1.y);
    *(unsigned int*)&g_hl16[ob] = f2_to_h2(u2.x, u2.y);
    *(unsigned int*)&g_hh16[ob] = f2_to_h2(u3.x, u3.y);
}

// ---------------- K2a: attention matrices (all heads parallel) --------------
// One CTA per (window, head). lh/hl loaded fp16, converted to fp32 in smem.
// Output stored [wh][n][m] as fp16 — 2x STG.128.
__global__ __launch_bounds__(256) void attn_mat_kernel(
    const float* __restrict__ dww, const float* __restrict__ dwb) {
    __shared__ float lh_s[HD * SROW];
    __shared__ float k_s[HD * SROW];
    __shared__ float q_s[HD * SROW];
    __shared__ float w_s[HD * 25];

    const int t  = threadIdx.x;
    const int wh = blockIdx.x;           // 0..4095
    const int w  = wh >> 3;
    const int h  = wh & 7;
    const int b  = w >> 8;
    const int wy = (w >> 4) & 15;
    const int wx = w & 15;
    const int dl = t >> 3;               // 0..31
    const int py = t & 7;                // 0..7

    {
        int ch   = b * DIMC + h * HD + dl;
        int base = (ch * H2 + wy * 8 + py) * H2 + wx * 8;
        int o0   = dl * SROW + py * 8;
        uint4 lv = *(const uint4*)&g_lh16[base];   // 8 halfs
        uint4 kv = *(const uint4*)&g_hl16[base];
        float2 l0 = __half22float2(*(__half2*)&lv.x);
        float2 l1 = __half22float2(*(__half2*)&lv.y);
        float2 l2 = __half22float2(*(__half2*)&lv.z);
        float2 l3 = __half22float2(*(__half2*)&lv.w);
        float2 k0 = __half22float2(*(__half2*)&kv.x);
        float2 k1 = __half22float2(*(__half2*)&kv.y);
        float2 k2 = __half22float2(*(__half2*)&kv.z);
        float2 k3 = __half22float2(*(__half2*)&kv.w);
        *(float4*)&lh_s[o0]     = make_float4(l0.x, l0.y, l1.x, l1.y);
        *(float4*)&lh_s[o0 + 4] = make_float4(l2.x, l2.y, l3.x, l3.y);
        *(float4*)&k_s[o0]      = make_float4(k0.x, k0.y, k1.x, k1.y);
        *(float4*)&k_s[o0 + 4]  = make_float4(k2.x, k2.y, k3.x, k3.y);
    }
    for (int i = t; i < HD * 25; i += 256) w_s[i] = dww[h * HD * 25 + i];
    __syncthreads();

    // ---- q = depthwise 5x5 conv on lh ----
    {
        float accq[8];
        float bias0 = __ldg(&dwb[h * HD + dl]);
        #pragma unroll
        for (int px = 0; px < 8; ++px) accq[px] = bias0;
        #pragma unroll
        for (int u = 0; u < 5; ++u) {
            int yy = py + u - 2;
            if (yy >= 0 && yy < 8) {
                float4 r0 = *(const float4*)&lh_s[dl * SROW + yy * 8];
                float4 r1 = *(const float4*)&lh_s[dl * SROW + yy * 8 + 4];
                float r[8] = {r0.x, r0.y, r0.z, r0.w, r1.x, r1.y, r1.z, r1.w};
                #pragma unroll
                for (int v = 0; v < 5; ++v) {
                    float wv = w_s[dl * 25 + u * 5 + v];
                    #pragma unroll
                    for (int px = 0; px < 8; ++px) {
                        int xx = px + v - 2;
                        if (xx >= 0 && xx < 8)
                            accq[px] += r[xx] * wv;
                    }
                }
            }
        }
        #pragma unroll
        for (int px = 0; px < 8; ++px) q_s[dl * SROW + py * 8 + px] = accq[px];
    }
    __syncthreads();

    // ---- attn = softmax(q.k * scale + bias), packed f32x2 QK ----
    {
        int n  = t >> 2;
        int mq = t & 3;
        ull acc2[8];
        #pragma unroll
        for (int i = 0; i < 8; ++i) acc2[i] = 0ull;

        #pragma unroll 4
        for (int d2 = 0; d2 < HD; ++d2) {
            float qd = q_s[d2 * SROW + n];
            ull pq = pack2(qd, qd);
            const float* kp = &k_s[d2 * SROW + mq * 16];
            ulonglong2 k01 = *(const ulonglong2*)(kp);
            ulonglong2 k23 = *(const ulonglong2*)(kp + 4);
            ulonglong2 k45 = *(const ulonglong2*)(kp + 8);
            ulonglong2 k67 = *(const ulonglong2*)(kp + 12);
            ffma2(acc2[0], pq, k01.x);
            ffma2(acc2[1], pq, k01.y);
            ffma2(acc2[2], pq, k23.x);
            ffma2(acc2[3], pq, k23.y);
            ffma2(acc2[4], pq, k45.x);
            ffma2(acc2[5], pq, k45.y);
            ffma2(acc2[6], pq, k67.x);
            ffma2(acc2[7], pq, k67.y);
        }

        float acc[16];
        #pragma unroll
        for (int i = 0; i < 8; ++i) {
            float2 u = unpack2(acc2[i]);
            acc[2 * i]     = u.x;
            acc[2 * i + 1] = u.y;
        }

        const float* bptr = &g_bias[h * 4096 + n * 64 + mq * 16];
        float mx = -1e30f;
        #pragma unroll
        for (int mi = 0; mi < 16; ++mi) {
            acc[mi] = acc[mi] * ATTN_SCALE + __ldg(&bptr[mi]);
            mx = fmaxf(mx, acc[mi]);
        }
        mx = fmaxf(mx, __shfl_xor_sync(0xffffffffu, mx, 1));
        mx = fmaxf(mx, __shfl_xor_sync(0xffffffffu, mx, 2));
        float s = 0.f;
        #pragma unroll
        for (int mi = 0; mi < 16; ++mi) {
            float e = __expf(acc[mi] - mx);
            acc[mi] = e;
            s += e;
        }
        s += __shfl_xor_sync(0xffffffffu, s, 1);
        s += __shfl_xor_sync(0xffffffffu, s, 2);
        float inv = 1.f / s;

        // ---- fp16 [n][m] layout: 16 halfs contiguous -> 2x STG.128 ----
        __half2 hb[8];
        #pragma unroll
        for (int g2 = 0; g2 < 8; ++g2)
            hb[g2] = __floats2half2_rn(acc[2 * g2] * inv, acc[2 * g2 + 1] * inv);
        __half* op = &g_attnh[wh * 4096 + n * 64 + mq * 16];
        *(uint4*)op       = *(uint4*)&hb[0];
        *(uint4*)(op + 8) = *(uint4*)&hb[4];
    }
}

// ---------------- K2b: sequential AV chain, 2 CTAs per window (d-split) ----
// fp16 attn tile ([n][m], AROWH=72), fp16 relu output. ll read fp32.
__global__ __launch_bounds__(128) void attn_av_kernel() {
    __shared__ float v_s[16 * NPIX];          // 4KB
    __shared__ float o_s[16 * NPIX];          // 4KB
    __shared__ __half attn_h[NPIX * AROWH];   // 9KB, fp16 [n][m] padded

    const int t    = threadIdx.x;           // 0..127
    const int wc   = blockIdx.x;            // 0..1023
    const int w    = wc >> 1;
    const int dbase = (wc & 1) * 16;        // d-half of this CTA
    const int b  = w >> 8;
    const int wy = (w >> 4) & 15;
    const int wx = w & 15;
    const int wp   = t >> 5;                // warp 0..3 -> local d rows 4wp..4wp+3
    const int lane = t & 31;                // n and n+32

    uint4 pa[4];    // prefetched fp16 attn tile
    float4 pl[2];   // prefetched ll chunk

    {
        const uint4* ap = (const uint4*)&g_attnh[(w * 8 + 0) * 4096];
        #pragma unroll
        for (int i = 0; i < 4; ++i)
            pa[i] = ap[t + 128 * i];
        #pragma unroll
        for (int i = 0; i < 2; ++i) {
            int c  = t + 128 * i;            // 0..255
            int d  = c >> 4;                 // 0..15 local
            int m0 = (c & 15) * 4;
            int ch = b * DIMC + 0 * HD + dbase + d;
            pl[i] = *(const float4*)&g_ll[(ch * H2 + wy * 8 + (m0 >> 3)) * H2
                                          + wx * 8 + (m0 & 7)];
        }
    }

    for (int h = 0; h < HEADS; ++h) {
        __syncthreads();

        // ---- stage fp16 attn into padded [n][m] smem ----
        #pragma unroll
        for (int i = 0; i < 4; ++i) {
            int c = t + 128 * i;             // 0..511: n = c>>3, m0 = (c&7)*8
            *(uint4*)&attn_h[(c >> 3) * AROWH + (c & 7) * 8] = pa[i];
        }
        #pragma unroll
        for (int i = 0; i < 2; ++i) {
            int c = t + 128 * i;
            float4 v4 = pl[i];
            if (h > 0) {
                float4 o4 = *(const float4*)&o_s[c * 4];
                v4.x += o4.x; v4.y += o4.y; v4.z += o4.z; v4.w += o4.w;
                int d  = c >> 4;
                int m0 = (c & 15) * 4;
                uint2 rr = make_uint2(f2_to_h2(fmaxf(o4.x, 0.f), fmaxf(o4.y, 0.f)),
                                      f2_to_h2(fmaxf(o4.z, 0.f), fmaxf(o4.w, 0.f)));
                *(uint2*)&g_atth[((h - 1) * HD + dbase + d) * PIXTOT + w * 64 + m0] = rr;
            }
            *(float4*)&v_s[c * 4] = v4;
        }

        if (h < HEADS - 1) {
            const uint4* ap = (const uint4*)&g_attnh[(w * 8 + h + 1) * 4096];
            #pragma unroll
            for (int i = 0; i < 4; ++i)
                pa[i] = ap[t + 128 * i];
            #pragma unroll
            for (int i = 0; i < 2; ++i) {
                int c  = t + 128 * i;
                int d  = c >> 4;
                int m0 = (c & 15) * 4;
                int ch = b * DIMC + (h + 1) * HD + dbase + d;
                pl[i] = *(const float4*)&g_ll[(ch * H2 + wy * 8 + (m0 >> 3)) * H2
                                              + wx * 8 + (m0 & 7)];
            }
        }
        __syncthreads();

        // ---- out[d][n] = sum_m v[d][m] * attn[n][m], 8-m steps ----
        ull acc2[4][2];
        #pragma unroll
        for (int j = 0; j < 4; ++j) { acc2[j][0] = 0ull; acc2[j][1] = 0ull; }

        #pragma unroll
        for (int m = 0; m < 64; m += 8) {
            uint4 alh = *(const uint4*)&attn_h[lane * AROWH + m];
            uint4 ahh = *(const uint4*)&attn_h[(lane + 32) * AROWH + m];
            ull AL0 = h2_to_pack2(alh.x), AL1 = h2_to_pack2(alh.y);
            ull AL2 = h2_to_pack2(alh.z), AL3 = h2_to_pack2(alh.w);
            ull AH0 = h2_to_pack2(ahh.x), AH1 = h2_to_pack2(ahh.y);
            ull AH2 = h2_to_pack2(ahh.z), AH3 = h2_to_pack2(ahh.w);

            #pragma unroll
            for (int j = 0; j < 4; ++j) {
                ulonglong2 va = *(const ulonglong2*)&v_s[(4 * wp + j) * 64 + m];
                ulonglong2 vb = *(const ulonglong2*)&v_s[(4 * wp + j) * 64 + m + 4];
                ffma2(acc2[j][0], va.x, AL0); ffma2(acc2[j][0], va.y, AL1);
                ffma2(acc2[j][0], vb.x, AL2); ffma2(acc2[j][0], vb.y, AL3);
                ffma2(acc2[j][1], va.x, AH0); ffma2(acc2[j][1], va.y, AH1);
                ffma2(acc2[j][1], vb.x, AH2); ffma2(acc2[j][1], vb.y, AH3);
            }
        }
        #pragma unroll
        for (int j = 0; j < 4; ++j) {
            float2 u0 = unpack2(acc2[j][0]);
            float2 u1 = unpack2(acc2[j][1]);
            o_s[(4 * wp + j) * 64 + lane]      = u0.x + u0.y;
            o_s[(4 * wp + j) * 64 + lane + 32] = u1.x + u1.y;
        }
    }

    // ---- epilogue: relu-store head 7 output (fp16) ----
    __syncthreads();
    #pragma unroll
    for (int i = 0; i < 2; ++i) {
        int c  = t + 128 * i;
        int d  = c >> 4;
        int m0 = (c & 15) * 4;
        float4 o4 = *(const float4*)&o_s[c * 4];
        uint2 rr = make_uint2(f2_to_h2(fmaxf(o4.x, 0.f), fmaxf(o4.y, 0.f)),
                              f2_to_h2(fmaxf(o4.z, 0.f), fmaxf(o4.w, 0.f)));
        *(uint2*)&g_atth[(7 * HD + dbase + d) * PIXTOT + w * 64 + m0] = rr;
    }
}

// ---------------- K3: fused proj GEMM + inverse wavelet ---------------------
// C[m][n] = W @ relu(attn_out) + bias computed in registers, then IWT applied
// directly in the epilogue (elementwise per (channel, window-pixel)): the 2x2
// output stamp needs only C[m][n], the fp16 bands at (m,n), and channel-m's
// filter. g_proj round-trip eliminated; iwt_kernel deleted.
__global__ __launch_bounds__(256) void proj_iwt_gemm(
    const float* __restrict__ Wm, const float* __restrict__ pb,
    const float* __restrict__ iwtf, float* __restrict__ out) {
    __shared__ float As[2][16 * PSROW];
    __shared__ float Bs[2][16 * PSROW];

    const int t  = threadIdx.x;
    const int n0 = blockIdx.x * 128;
    const int m0 = blockIdx.y * 128;
    const int tx = t & 15, ty = t >> 4;

    const int am = t >> 1;
    const int ak = (t & 1) * 8;
    const int bk = t >> 4;
    const int bn = (t & 15) * 8;

    ull acc2[8][4];
    #pragma unroll
    for (int i = 0; i < 8; ++i)
        #pragma unroll
        for (int j = 0; j < 4; ++j) acc2[i][j] = 0ull;

    float4 pa0 = *(const float4*)&Wm[(m0 + am) * 256 + ak];
    float4 pa1 = *(const float4*)&Wm[(m0 + am) * 256 + ak + 4];
    uint4  pbv = *(const uint4*)&g_atth[bk * PIXTOT + n0 + bn];   // 8 halfs

    for (int kt = 0; kt < 16; ++kt) {
        float* as = As[kt & 1];
        float* bs = Bs[kt & 1];
        as[(ak + 0) * PSROW + am] = pa0.x;
        as[(ak + 1) * PSROW + am] = pa0.y;
        as[(ak + 2) * PSROW + am] = pa0.z;
        as[(ak + 3) * PSROW + am] = pa0.w;
        as[(ak + 4) * PSROW + am] = pa1.x;
        as[(ak + 5) * PSROW + am] = pa1.y;
        as[(ak + 6) * PSROW + am] = pa1.z;
        as[(ak + 7) * PSROW + am] = pa1.w;
        {
            float2 b0 = __half22float2(*(__half2*)&pbv.x);
            float2 b1 = __half22float2(*(__half2*)&pbv.y);
            float2 b2 = __half22float2(*(__half2*)&pbv.z);
            float2 b3 = __half22float2(*(__half2*)&pbv.w);
            *(float4*)&bs[bk * PSROW + bn]     = make_float4(b0.x, b0.y, b1.x, b1.y);
            *(float4*)&bs[bk * PSROW + bn + 4] = make_float4(b2.x, b2.y, b3.x, b3.y);
        }

        if (kt < 15) {
            int k0 = (kt + 1) * 16;
            pa0 = *(const float4*)&Wm[(m0 + am) * 256 + k0 + ak];
            pa1 = *(const float4*)&Wm[(m0 + am) * 256 + k0 + ak + 4];
            pbv = *(const uint4*)&g_atth[(k0 + bk) * PIXTOT + n0 + bn];
        }
        __syncthreads();   // staging of buf[kt&1] complete

        #pragma unroll
        for (int k = 0; k < 16; ++k) {
            float4 a0 = *(const float4*)&as[k * PSROW + ty * 4];
            float4 a1 = *(const float4*)&as[k * PSROW + 64 + ty * 4];
            ulonglong2 b01 = *(const ulonglong2*)&bs[k * PSROW + tx * 4];
            ulonglong2 b23 = *(const ulonglong2*)&bs[k * PSROW + 64 + tx * 4];
            float av[8] = {a0.x, a0.y, a0.z, a0.w, a1.x, a1.y, a1.z, a1.w};
            #pragma unroll
            for (int i = 0; i < 8; ++i) {
                ull pav = pack2(av[i], av[i]);
                ffma2(acc2[i][0], pav, b01.x);
                ffma2(acc2[i][1], pav, b01.y);
                ffma2(acc2[i][2], pav, b23.x);
                ffma2(acc2[i][3], pav, b23.y);
            }
        }
        // no trailing barrier: next staging targets the other buffer
    }

    // ---- fused epilogue: ll = C + bias; apply IWT stamp; write output ----
    #pragma unroll
    for (int i = 0; i < 8; ++i) {
        int m = m0 + ((i < 4) ? (ty * 4 + i) : (64 + ty * 4 + i - 4));  // channel
        float bias = __ldg(&pb[m]);
        const float4 F0 = __ldg((const float4*)&iwtf[(4 * m + 0) * 4]);
        const float4 F1 = __ldg((const float4*)&iwtf[(4 * m + 1) * 4]);
        const float4 F2 = __ldg((const float4*)&iwtf[(4 * m + 2) * 4]);
        const float4 F3 = __ldg((const float4*)&iwtf[(4 * m + 3) * 4]);

        float2 c0 = unpack2(acc2[i][0]);
        float2 c1 = unpack2(acc2[i][1]);
        float2 c2 = unpack2(acc2[i][2]);
        float2 c3 = unpack2(acc2[i][3]);
        float llv[2][4] = {{c0.x + bias, c0.y + bias, c1.x + bias, c1.y + bias},
                           {c2.x + bias, c2.y + bias, c3.x + bias, c3.y + bias}};

        #pragma unroll
        for (int g = 0; g < 2; ++g) {
            int nb = n0 + g * 64 + tx * 4;       // 4 consecutive window-pixels
            int w  = nb >> 6;
            int pp = nb & 63;
            int py = pp >> 3, px = pp & 7;       // px 4-aligned
            int bq = w >> 8, wy = (w >> 4) & 15, wx = w & 15;
            int y  = wy * 8 + py;
            int x  = wx * 8 + px;
            int bc = bq * DIMC + m;
            int bb = (bc * H2 + y) * H2 + x;

            ull lh4 = *(const ull*)&g_lh16[bb];   // 4 halfs
            ull hl4 = *(const ull*)&g_hl16[bb];
            ull hh4 = *(const ull*)&g_hh16[bb];
            float2 lhA = __half22float2(*(__half2*)&lh4);
            float2 lhB = __half22float2(((__half2*)&lh4)[1]);
            float2 hlA = __half22float2(*(__half2*)&hl4);
            float2 hlB = __half22float2(((__half2*)&hl4)[1]);
            float2 hhA = __half22float2(*(__half2*)&hh4);
            float2 hhB = __half22float2(((__half2*)&hh4)[1]);
            float lh[4] = {lhA.x, lhA.y, lhB.x, lhB.y};
            float hl[4] = {hlA.x, hlA.y, hlB.x, hlB.y};
            float hh[4] = {hhA.x, hhA.y, hhB.x, hhB.y};

            float r0[8], r1[8];
            #pragma unroll
            for (int j = 0; j < 4; ++j) {
                float L = llv[g][j];
                r0[2 * j]     = L * F0.x + lh[j] * F1.x + hl[j] * F2.x + hh[j] * F3.x;
                r0[2 * j + 1] = L * F0.y + lh[j] * F1.y + hl[j] * F2.y + hh[j] * F3.y;
                r1[2 * j]     = L * F0.z + lh[j] * F1.z + hl[j] * F2.z + hh[j] * F3.z;
                r1[2 * j + 1] = L * F0.w + lh[j] * F1.w + hl[j] * F2.w + hh[j] * F3.w;
            }
            int ob = (bc * RESV + 2 * y) * RESV + 2 * x;
            *(float4*)&out[ob]            = *(float4*)&r0[0];
            *(float4*)&out[ob + 4]        = *(float4*)&r0[4];
            *(float4*)&out[ob + RESV]     = *(float4*)&r1[0];
            *(float4*)&out[ob + RESV + 4] = *(float4*)&r1[4];
        }
    }
}

// ---------------- launch ----------------------------------------------------
extern "C" void kernel_launch(void* const* d_in, const int* in_sizes, int n_in,
                              void* d_out, int out_size) {
    const float* x    = (const float*)d_in[0];
    const float* wtf  = (const float*)d_in[1];
    const float* iwtf = (const float*)d_in[2];
    const float* dww  = (const float*)d_in[3];
    const float* dwb  = (const float*)d_in[4];
    const float* pw   = (const float*)d_in[5];
    const float* pb   = (const float*)d_in[6];
    const float* ab   = (const float*)d_in[7];
    const int*   bidx = (const int*)d_in[8];
    float* out = (float*)d_out;

    bias_kernel<<<128, 256>>>(ab, bidx);
    wt_kernel<<<dim3(64, 512), 128>>>(x, wtf);
    attn_mat_kernel<<<4096, 256>>>(dww, dwb);
    attn_av_kernel<<<1024, 128>>>();
    proj_iwt_gemm<<<dim3(256, 2), 256>>>(pw, pb, iwtf, out);
}